// round 4
// baseline (speedup 1.0000x reference)
#include <cuda_runtime.h>
#include <cuda_bf16.h>
#include <math.h>
#include <stdint.h>

#define D_IN   768
#define D_OUT  256
#define NEXP   8
#define NT_MAX 32768

// ---------------- device scratch (no allocs allowed) ----------------
__device__ int      g_cnt[NEXP];
__device__ int      g_tok[NEXP * NT_MAX];
__device__ float    g_wt [NEXP * NT_MAX];
__device__ uint32_t g_xtf[NT_MAX * D_IN];            // x converted to tf32 (96 MB)
__device__ uint32_t g_Wc [NEXP * D_IN * D_OUT];      // W converted to tf32, [e][k][n]

__device__ __forceinline__ uint32_t smem_u32(const void* p) {
    uint32_t a;
    asm("{ .reg .u64 t; cvta.to.shared.u64 t, %1; cvt.u32.u64 %0, t; }" : "=r"(a) : "l"(p));
    return a;
}
__device__ __forceinline__ uint32_t f2tf32(float f) {
    uint32_t r;
    asm("cvt.rna.tf32.f32 %0, %1;" : "=r"(r) : "f"(f));
    return r;
}

// ---------------- kernel 1: convert W to tf32 + zero counters ----------------
__global__ void convert_w_kernel(const float* __restrict__ eW) {
    if (blockIdx.x == 0 && threadIdx.x < NEXP) g_cnt[threadIdx.x] = 0;
    size_t i = ((size_t)blockIdx.x * blockDim.x + threadIdx.x) * 4;
    if (i < (size_t)NEXP * D_IN * D_OUT) {
        float4 v = *(const float4*)(eW + i);
        uint4 u = make_uint4(f2tf32(v.x), f2tf32(v.y), f2tf32(v.z), f2tf32(v.w));
        *(uint4*)(g_Wc + i) = u;
    }
}

// ---------------- kernel 2: gating + x->tf32 conversion ----------------
__global__ void gate_kernel(const float* __restrict__ x,
                            const float* __restrict__ gW,
                            const float* __restrict__ gb,
                            int NT) {
    __shared__ float sWt[NEXP * D_IN];   // transposed: [e][k], 24 KB
    for (int i = threadIdx.x; i < D_IN * NEXP; i += blockDim.x)
        sWt[(i & 7) * D_IN + (i >> 3)] = gW[i];
    __syncthreads();

    int warp = threadIdx.x >> 5, lane = threadIdx.x & 31;
    int token = blockIdx.x * (blockDim.x >> 5) + warp;
    if (token >= NT) return;

    const float4* xr4 = (const float4*)(x + (size_t)token * D_IN);
    uint4* xo = (uint4*)(g_xtf + (size_t)token * D_IN);

    float acc[NEXP];
#pragma unroll
    for (int e = 0; e < NEXP; e++) acc[e] = 0.f;

#pragma unroll
    for (int j = 0; j < D_IN / 128; j++) {          // 6 iters
        int idx = lane + j * 32;                     // float4 index
        float4 v = xr4[idx];
        int k = idx * 4;
#pragma unroll
        for (int e = 0; e < NEXP; e++) {
            const float* w = &sWt[e * D_IN + k];
            acc[e] = fmaf(v.x, w[0], acc[e]);
            acc[e] = fmaf(v.y, w[1], acc[e]);
            acc[e] = fmaf(v.z, w[2], acc[e]);
            acc[e] = fmaf(v.w, w[3], acc[e]);
        }
        xo[idx] = make_uint4(f2tf32(v.x), f2tf32(v.y), f2tf32(v.z), f2tf32(v.w));
    }
#pragma unroll
    for (int off = 16; off > 0; off >>= 1)
#pragma unroll
        for (int e = 0; e < NEXP; e++)
            acc[e] += __shfl_xor_sync(0xffffffffu, acc[e], off);

    if (lane == 0) {
        float l[NEXP];
#pragma unroll
        for (int e = 0; e < NEXP; e++) l[e] = acc[e] + gb[e];
        float m = l[0];
#pragma unroll
        for (int e = 1; e < NEXP; e++) m = fmaxf(m, l[e]);
        float s = 0.f, w[NEXP];
#pragma unroll
        for (int e = 0; e < NEXP; e++) { w[e] = __expf(l[e] - m); s += w[e]; }
        float inv = 1.f / s;
        int i0 = 0;
#pragma unroll
        for (int e = 1; e < NEXP; e++) if (l[e] > l[i0]) i0 = e;
        int i1 = (i0 == 0) ? 1 : 0;
#pragma unroll
        for (int e = 0; e < NEXP; e++) if (e != i0 && l[e] > l[i1]) i1 = e;

        int p0 = atomicAdd(&g_cnt[i0], 1);
        g_tok[i0 * NT_MAX + p0] = token;  g_wt[i0 * NT_MAX + p0] = w[i0] * inv;
        int p1 = atomicAdd(&g_cnt[i1], 1);
        g_tok[i1 * NT_MAX + p1] = token;  g_wt[i1 * NT_MAX + p1] = w[i1] * inv;
    }
}

// ---------------- kernel 3: TF32 mma.sync gathered GEMM, cp.async pipeline ----
// CTA tile M=256, N=128, BK=16. 8 warps (4m x 2n), warp tile 64x64.
// SMEM per stage: A [256][20]u32 = 20480 B, B [16][136]u32 = 8704 B. 4 stages.
#define BKS      16
#define NSTAGE   (D_IN / BKS)     // 48
#define PSTAGES  4
#define A_STAGE  20480
#define B_STAGE  8704
#define SM_B_OFF (PSTAGES * A_STAGE)               // 81920
#define SM_SZ    (SM_B_OFF + PSTAGES * B_STAGE)    // 116736

#define CP_ASYNC(dst, src, sz) \
    asm volatile("cp.async.cg.shared.global [%0], [%1], 16, %2;" \
                 :: "r"(dst), "l"(src), "r"(sz) : "memory")
#define CP_ASYNC16(dst, src) \
    asm volatile("cp.async.cg.shared.global [%0], [%1], 16;" \
                 :: "r"(dst), "l"(src) : "memory")
#define CP_COMMIT()  asm volatile("cp.async.commit_group;" ::: "memory")
#define CP_WAIT(n)   asm volatile("cp.async.wait_group %0;" :: "n"(n) : "memory")

__global__ __launch_bounds__(256, 1)
void moe_gemm_tf32(const float* __restrict__ eb, float* __restrict__ out) {
    const int e = blockIdx.z;
    const int cnt = g_cnt[e];
    const int mbase = blockIdx.y * 256;
    if (mbase >= cnt) return;
    const int nbase = blockIdx.x * 128;

    extern __shared__ __align__(1024) char smem[];
    const uint32_t sb = smem_u32(smem);

    const int tid  = threadIdx.x;
    const int wid  = tid >> 5;
    const int lane = tid & 31;
    const int wm = wid >> 1, wn = wid & 1;
    const int grp = lane >> 2, tig = lane & 3;

    // --- A chunks: 1024 slots (256 rows x 4 x 16B), 4 per thread ---
    const uint32_t* asrc[4];
    uint32_t adst[4], asz[4];
#pragma unroll
    for (int i = 0; i < 4; i++) {
        int c = tid + i * 256;
        int r = c >> 2, q = c & 3;
        int grow = mbase + r;
        bool v = grow < cnt;
        asrc[i] = g_xtf + (v ? (size_t)g_tok[e * NT_MAX + grow] * D_IN : 0) + q * 4;
        adst[i] = sb + (uint32_t)(r * 80 + q * 16);
        asz[i]  = v ? 16u : 0u;
    }
    // --- B chunks: 512 slots (16 rows x 32 x 16B), 2 per thread ---
    const uint32_t* bsrc[2];
    uint32_t bdst[2];
#pragma unroll
    for (int i = 0; i < 2; i++) {
        int c = tid + i * 256;
        int kr = c >> 5, cq = c & 31;
        bsrc[i] = g_Wc + ((size_t)e * D_IN + kr) * D_OUT + nbase + cq * 4;
        bdst[i] = sb + SM_B_OFF + (uint32_t)(kr * 544 + cq * 16);
    }

    float acc[4][8][4];
#pragma unroll
    for (int mi = 0; mi < 4; mi++)
#pragma unroll
        for (int ni = 0; ni < 8; ni++)
#pragma unroll
            for (int c = 0; c < 4; c++) acc[mi][ni][c] = 0.f;

    auto issue = [&](int s) {
        const uint32_t ao = (uint32_t)((s & (PSTAGES - 1)) * A_STAGE);
        const uint32_t bo = (uint32_t)((s & (PSTAGES - 1)) * B_STAGE);
        const int ka = s * BKS;               // u32 offset into A rows
        const int kb = s * BKS * D_OUT;       // u32 offset into B
#pragma unroll
        for (int i = 0; i < 4; i++) CP_ASYNC(adst[i] + ao, asrc[i] + ka, asz[i]);
#pragma unroll
        for (int i = 0; i < 2; i++) CP_ASYNC16(bdst[i] + bo, bsrc[i] + kb);
    };

    // prologue: stages 0..2
#pragma unroll
    for (int s = 0; s < PSTAGES - 1; s++) { issue(s); CP_COMMIT(); }

    for (int t = 0; t < NSTAGE; t++) {
        CP_WAIT(PSTAGES - 2);
        __syncthreads();

        const uint32_t* As = (const uint32_t*)(smem + (t & (PSTAGES - 1)) * A_STAGE);
        const uint32_t* Bs = (const uint32_t*)(smem + SM_B_OFF + (t & (PSTAGES - 1)) * B_STAGE);

#pragma unroll
        for (int kk = 0; kk < BKS; kk += 8) {
            uint32_t a[4][4];
#pragma unroll
            for (int mi = 0; mi < 4; mi++) {
                int r0 = wm * 64 + mi * 16 + grp;
                a[mi][0] = As[r0 * 20 + kk + tig];
                a[mi][1] = As[(r0 + 8) * 20 + kk + tig];
                a[mi][2] = As[r0 * 20 + kk + tig + 4];
                a[mi][3] = As[(r0 + 8) * 20 + kk + tig + 4];
            }
#pragma unroll
            for (int ni = 0; ni < 8; ni++) {
                int n0 = wn * 64 + ni * 8 + grp;
                uint32_t b0 = Bs[(kk + tig) * 136 + n0];
                uint32_t b1 = Bs[(kk + tig + 4) * 136 + n0];
#pragma unroll
                for (int mi = 0; mi < 4; mi++) {
                    asm volatile(
                        "mma.sync.aligned.m16n8k8.row.col.f32.tf32.tf32.f32 "
                        "{%0,%1,%2,%3}, {%4,%5,%6,%7}, {%8,%9}, {%0,%1,%2,%3};"
                        : "+f"(acc[mi][ni][0]), "+f"(acc[mi][ni][1]),
                          "+f"(acc[mi][ni][2]), "+f"(acc[mi][ni][3])
                        : "r"(a[mi][0]), "r"(a[mi][1]), "r"(a[mi][2]), "r"(a[mi][3]),
                          "r"(b0), "r"(b1));
                }
            }
        }

        if (t + PSTAGES - 1 < NSTAGE) issue(t + PSTAGES - 1);
        CP_COMMIT();
    }

    // --- epilogue ---
    float2 bias[8];
#pragma unroll
    for (int ni = 0; ni < 8; ni++)
        bias[ni] = *(const float2*)(eb + e * D_OUT + nbase + wn * 64 + ni * 8 + tig * 2);

#pragma unroll
    for (int mi = 0; mi < 4; mi++) {
        int rbase = wm * 64 + mi * 16 + grp;
#pragma unroll
        for (int h = 0; h < 2; h++) {
            int grow = mbase + rbase + h * 8;
            if (grow < cnt) {
                int   token = g_tok[e * NT_MAX + grow];
                float w     = g_wt [e * NT_MAX + grow];
                float* orow = out + (size_t)token * D_OUT + nbase + wn * 64 + tig * 2;
#pragma unroll
                for (int ni = 0; ni < 8; ni++) {
                    float v0 = w * (acc[mi][ni][h * 2]     + bias[ni].x);
                    float v1 = w * (acc[mi][ni][h * 2 + 1] + bias[ni].y);
                    asm volatile("red.global.add.v2.f32 [%0], {%1, %2};"
                                 :: "l"(orow + ni * 8), "f"(v0), "f"(v1) : "memory");
                }
            }
        }
    }
}

// ---------------- launch ----------------
extern "C" void kernel_launch(void* const* d_in, const int* in_sizes, int n_in,
                              void* d_out, int out_size) {
    const float* x  = (const float*)d_in[0];
    const float* gW = (const float*)d_in[1];
    const float* gb = (const float*)d_in[2];
    const float* eW = (const float*)d_in[3];
    const float* eb = (const float*)d_in[4];
    float* out = (float*)d_out;

    const int NT = in_sizes[0] / D_IN;   // 32768

    cudaFuncSetAttribute(moe_gemm_tf32, cudaFuncAttributeMaxDynamicSharedMemorySize, SM_SZ);

    cudaMemsetAsync(d_out, 0, (size_t)out_size * sizeof(float), 0);

    const int wTotal = NEXP * D_IN * D_OUT / 4;           // float4 units
    convert_w_kernel<<<(wTotal + 255) / 256, 256>>>(eW);

    gate_kernel<<<(NT + 7) / 8, 256>>>(x, gW, gb, NT);

    dim3 grid(D_OUT / 128, (NT + 255) / 256, NEXP);       // early exit on empty m-tiles
    moe_gemm_tf32<<<grid, 256, SM_SZ>>>(eb, out);
}

// round 5
// speedup vs baseline: 1.4007x; 1.4007x over previous
#include <cuda_runtime.h>
#include <cuda_fp16.h>
#include <math.h>
#include <stdint.h>

#define D_IN   768
#define D_OUT  256
#define NEXP   8
#define NT_MAX 32768

// ---------------- device scratch (no allocs allowed) ----------------
__device__ int    g_cnt[NEXP];
__device__ int    g_tok[NEXP * NT_MAX];
__device__ float  g_wt [NEXP * NT_MAX];
__device__ __half g_xh [NT_MAX * D_IN];              // x in fp16 (48 MB)
__device__ __half g_Wh [NEXP * D_OUT * D_IN];        // W in fp16, transposed [e][n][k]

__device__ __forceinline__ uint32_t smem_u32(const void* p) {
    uint32_t a;
    asm("{ .reg .u64 t; cvta.to.shared.u64 t, %1; cvt.u32.u64 %0, t; }" : "=r"(a) : "l"(p));
    return a;
}

// ---------------- kernel 1: W -> fp16 transposed + zero counters ----------------
__global__ void convert_w_kernel(const float* __restrict__ eW) {
    if (blockIdx.x == 0 && blockIdx.y == 0 && blockIdx.z == 0 &&
        threadIdx.y == 0 && threadIdx.x < NEXP) g_cnt[threadIdx.x] = 0;

    __shared__ float t[32][33];
    int e = blockIdx.z, k0 = blockIdx.y * 32, n0 = blockIdx.x * 32;
    const float* W = eW + (size_t)e * D_IN * D_OUT;
    __half* Wh = g_Wh + (size_t)e * D_OUT * D_IN;
#pragma unroll
    for (int j = 0; j < 4; j++)
        t[threadIdx.y + j * 8][threadIdx.x] =
            W[(size_t)(k0 + threadIdx.y + j * 8) * D_OUT + n0 + threadIdx.x];
    __syncthreads();
#pragma unroll
    for (int j = 0; j < 4; j++)
        Wh[(size_t)(n0 + threadIdx.y + j * 8) * D_IN + k0 + threadIdx.x] =
            __float2half_rn(t[threadIdx.x][threadIdx.y + j * 8]);
}

// ---------------- kernel 2: gating + x -> fp16 ----------------
__global__ void gate_kernel(const float* __restrict__ x,
                            const float* __restrict__ gW,
                            const float* __restrict__ gb,
                            int NT) {
    __shared__ float sWt[NEXP * D_IN];   // transposed: [e][k]
    for (int i = threadIdx.x; i < D_IN * NEXP; i += blockDim.x)
        sWt[(i & 7) * D_IN + (i >> 3)] = gW[i];
    __syncthreads();

    int warp = threadIdx.x >> 5, lane = threadIdx.x & 31;
    int token = blockIdx.x * (blockDim.x >> 5) + warp;
    if (token >= NT) return;

    const float4* xr4 = (const float4*)(x + (size_t)token * D_IN);
    uint2* xo = (uint2*)(g_xh + (size_t)token * D_IN);

    float acc[NEXP];
#pragma unroll
    for (int e = 0; e < NEXP; e++) acc[e] = 0.f;

#pragma unroll
    for (int j = 0; j < D_IN / 128; j++) {          // 6 iters
        int idx = lane + j * 32;                     // float4 index
        float4 v = xr4[idx];
        int k = idx * 4;
#pragma unroll
        for (int e = 0; e < NEXP; e++) {
            const float* w = &sWt[e * D_IN + k];
            acc[e] = fmaf(v.x, w[0], acc[e]);
            acc[e] = fmaf(v.y, w[1], acc[e]);
            acc[e] = fmaf(v.z, w[2], acc[e]);
            acc[e] = fmaf(v.w, w[3], acc[e]);
        }
        __half2 h0 = __floats2half2_rn(v.x, v.y);
        __half2 h1 = __floats2half2_rn(v.z, v.w);
        uint2 u;
        u.x = *(uint32_t*)&h0;  u.y = *(uint32_t*)&h1;
        xo[idx] = u;
    }
#pragma unroll
    for (int off = 16; off > 0; off >>= 1)
#pragma unroll
        for (int e = 0; e < NEXP; e++)
            acc[e] += __shfl_xor_sync(0xffffffffu, acc[e], off);

    if (lane == 0) {
        float l[NEXP];
#pragma unroll
        for (int e = 0; e < NEXP; e++) l[e] = acc[e] + gb[e];
        float m = l[0];
#pragma unroll
        for (int e = 1; e < NEXP; e++) m = fmaxf(m, l[e]);
        float s = 0.f, w[NEXP];
#pragma unroll
        for (int e = 0; e < NEXP; e++) { w[e] = __expf(l[e] - m); s += w[e]; }
        float inv = 1.f / s;
        int i0 = 0;
#pragma unroll
        for (int e = 1; e < NEXP; e++) if (l[e] > l[i0]) i0 = e;
        int i1 = (i0 == 0) ? 1 : 0;
#pragma unroll
        for (int e = 0; e < NEXP; e++) if (e != i0 && l[e] > l[i1]) i1 = e;

        int p0 = atomicAdd(&g_cnt[i0], 1);
        g_tok[i0 * NT_MAX + p0] = token;  g_wt[i0 * NT_MAX + p0] = w[i0] * inv;
        int p1 = atomicAdd(&g_cnt[i1], 1);
        g_tok[i1 * NT_MAX + p1] = token;  g_wt[i1 * NT_MAX + p1] = w[i1] * inv;
    }
}

// ---------------- kernel 3: FP16 mma.sync gathered GEMM, cp.async pipeline ----
// CTA tile M=256, N=128, BK=32 (halfs). 8 warps (4m x 2n), warp tile 64x64.
// A smem [256 rows][40 halfs] (pitch 80B, rows 0..31 used = BK=32 + pad 8).
// B smem [128 n][40 halfs]. Pitch 40 halfs => banks (r*20 + tig) mod 32 distinct.
#define BKS      32
#define NSTAGE   (D_IN / BKS)     // 24
#define PSTAGES  4
#define A_STAGE  20480            // 256 * 80
#define B_STAGE  10240            // 128 * 80
#define SM_B_OFF (PSTAGES * A_STAGE)               // 81920
#define SM_SZ    (SM_B_OFF + PSTAGES * B_STAGE)    // 122880

#define CP_ASYNC_Z(dst, src, sz) \
    asm volatile("cp.async.cg.shared.global [%0], [%1], 16, %2;" \
                 :: "r"(dst), "l"(src), "r"(sz) : "memory")
#define CP_ASYNC16(dst, src) \
    asm volatile("cp.async.cg.shared.global [%0], [%1], 16;" \
                 :: "r"(dst), "l"(src) : "memory")
#define CP_COMMIT()  asm volatile("cp.async.commit_group;" ::: "memory")
#define CP_WAIT(n)   asm volatile("cp.async.wait_group %0;" :: "n"(n) : "memory")

__global__ __launch_bounds__(256, 1)
void moe_gemm_f16(const float* __restrict__ eb, float* __restrict__ out) {
    const int e = blockIdx.z;
    const int cnt = g_cnt[e];
    const int mbase = blockIdx.y * 256;
    if (mbase >= cnt) return;
    const int nbase = blockIdx.x * 128;

    extern __shared__ __align__(1024) char smem[];
    const uint32_t sb = smem_u32(smem);

    const int tid  = threadIdx.x;
    const int wid  = tid >> 5;
    const int lane = tid & 31;
    const int wm = wid >> 1, wn = wid & 1;
    const int grp = lane >> 2, tig = lane & 3;

    // --- A chunks: 1024 slots (256 rows x 4 x 16B=8 halfs), 4 per thread ---
    const __half* asrc[4];
    uint32_t adst[4], asz[4];
#pragma unroll
    for (int i = 0; i < 4; i++) {
        int c = tid + i * 256;
        int r = c >> 2, q = c & 3;
        int grow = mbase + r;
        bool v = grow < cnt;
        asrc[i] = g_xh + (v ? (size_t)g_tok[e * NT_MAX + grow] * D_IN : 0) + q * 8;
        adst[i] = sb + (uint32_t)(r * 80 + q * 16);
        asz[i]  = v ? 16u : 0u;
    }
    // --- B chunks: 512 slots (128 n x 4 x 8 halfs), 2 per thread ---
    const __half* bsrc[2];
    uint32_t bdst[2];
#pragma unroll
    for (int i = 0; i < 2; i++) {
        int c = tid + i * 256;
        int n = c >> 2, q = c & 3;
        bsrc[i] = g_Wh + ((size_t)e * D_OUT + nbase + n) * D_IN + q * 8;
        bdst[i] = sb + SM_B_OFF + (uint32_t)(n * 80 + q * 16);
    }

    float acc[4][8][4];
#pragma unroll
    for (int mi = 0; mi < 4; mi++)
#pragma unroll
        for (int ni = 0; ni < 8; ni++)
#pragma unroll
            for (int c = 0; c < 4; c++) acc[mi][ni][c] = 0.f;

    auto issue = [&](int s) {
        const uint32_t ao = (uint32_t)((s & (PSTAGES - 1)) * A_STAGE);
        const uint32_t bo = (uint32_t)((s & (PSTAGES - 1)) * B_STAGE);
        const int k0 = s * BKS;                  // half offset
#pragma unroll
        for (int i = 0; i < 4; i++) CP_ASYNC_Z(adst[i] + ao, asrc[i] + k0, asz[i]);
#pragma unroll
        for (int i = 0; i < 2; i++) CP_ASYNC16(bdst[i] + bo, bsrc[i] + k0);
    };

#pragma unroll
    for (int s = 0; s < PSTAGES - 1; s++) { issue(s); CP_COMMIT(); }

    for (int t = 0; t < NSTAGE; t++) {
        CP_WAIT(PSTAGES - 2);
        __syncthreads();

        const __half* As = (const __half*)(smem + (t & (PSTAGES - 1)) * A_STAGE);
        const __half* Bsn = (const __half*)(smem + SM_B_OFF + (t & (PSTAGES - 1)) * B_STAGE);

#pragma unroll
        for (int kk = 0; kk < BKS; kk += 16) {
            uint32_t a[4][4];
#pragma unroll
            for (int mi = 0; mi < 4; mi++) {
                int r0 = wm * 64 + mi * 16 + grp;
                a[mi][0] = *(const uint32_t*)&As[r0 * 40 + kk + 2 * tig];
                a[mi][1] = *(const uint32_t*)&As[(r0 + 8) * 40 + kk + 2 * tig];
                a[mi][2] = *(const uint32_t*)&As[r0 * 40 + kk + 2 * tig + 8];
                a[mi][3] = *(const uint32_t*)&As[(r0 + 8) * 40 + kk + 2 * tig + 8];
            }
#pragma unroll
            for (int ni = 0; ni < 8; ni++) {
                int n0 = wn * 64 + ni * 8 + grp;
                uint32_t b0 = *(const uint32_t*)&Bsn[n0 * 40 + kk + 2 * tig];
                uint32_t b1 = *(const uint32_t*)&Bsn[n0 * 40 + kk + 2 * tig + 8];
#pragma unroll
                for (int mi = 0; mi < 4; mi++) {
                    asm volatile(
                        "mma.sync.aligned.m16n8k16.row.col.f32.f16.f16.f32 "
                        "{%0,%1,%2,%3}, {%4,%5,%6,%7}, {%8,%9}, {%0,%1,%2,%3};"
                        : "+f"(acc[mi][ni][0]), "+f"(acc[mi][ni][1]),
                          "+f"(acc[mi][ni][2]), "+f"(acc[mi][ni][3])
                        : "r"(a[mi][0]), "r"(a[mi][1]), "r"(a[mi][2]), "r"(a[mi][3]),
                          "r"(b0), "r"(b1));
                }
            }
        }

        if (t + PSTAGES - 1 < NSTAGE) issue(t + PSTAGES - 1);
        CP_COMMIT();
    }

    // --- epilogue: out[token] += w * (acc + bias), two contributions/elt ---
    float2 bias[8];
#pragma unroll
    for (int ni = 0; ni < 8; ni++)
        bias[ni] = *(const float2*)(eb + e * D_OUT + nbase + wn * 64 + ni * 8 + tig * 2);

#pragma unroll
    for (int mi = 0; mi < 4; mi++) {
        int rbase = wm * 64 + mi * 16 + grp;
#pragma unroll
        for (int h = 0; h < 2; h++) {
            int grow = mbase + rbase + h * 8;
            if (grow < cnt) {
                int   token = g_tok[e * NT_MAX + grow];
                float w     = g_wt [e * NT_MAX + grow];
                float* orow = out + (size_t)token * D_OUT + nbase + wn * 64 + tig * 2;
#pragma unroll
                for (int ni = 0; ni < 8; ni++) {
                    float v0 = w * (acc[mi][ni][h * 2]     + bias[ni].x);
                    float v1 = w * (acc[mi][ni][h * 2 + 1] + bias[ni].y);
                    asm volatile("red.global.add.v2.f32 [%0], {%1, %2};"
                                 :: "l"(orow + ni * 8), "f"(v0), "f"(v1) : "memory");
                }
            }
        }
    }
}

// ---------------- launch ----------------
extern "C" void kernel_launch(void* const* d_in, const int* in_sizes, int n_in,
                              void* d_out, int out_size) {
    const float* x  = (const float*)d_in[0];
    const float* gW = (const float*)d_in[1];
    const float* gb = (const float*)d_in[2];
    const float* eW = (const float*)d_in[3];
    const float* eb = (const float*)d_in[4];
    float* out = (float*)d_out;

    const int NT = in_sizes[0] / D_IN;   // 32768

    cudaFuncSetAttribute(moe_gemm_f16, cudaFuncAttributeMaxDynamicSharedMemorySize, SM_SZ);

    cudaMemsetAsync(d_out, 0, (size_t)out_size * sizeof(float), 0);

    dim3 tgrid(D_OUT / 32, D_IN / 32, NEXP);
    convert_w_kernel<<<tgrid, dim3(32, 8)>>>(eW);

    gate_kernel<<<(NT + 7) / 8, 256>>>(x, gW, gb, NT);

    dim3 grid(D_OUT / 128, (NT + 255) / 256, NEXP);   // early exit on empty m-tiles
    moe_gemm_f16<<<grid, 256, SM_SZ>>>(eb, out);
}

// round 6
// speedup vs baseline: 1.4878x; 1.0622x over previous
#include <cuda_runtime.h>
#include <cuda_fp16.h>
#include <math.h>
#include <stdint.h>

#define D_IN   768
#define D_OUT  256
#define NEXP   8
#define NT_MAX 32768

// ---------------- device scratch (no allocs allowed) ----------------
__device__ int    g_cnt[NEXP];
__device__ int    g_tok[NEXP * NT_MAX];
__device__ float  g_wt [NEXP * NT_MAX];
__device__ __half g_xh [NT_MAX * D_IN];              // x in fp16 (48 MB)
__device__ __half g_Wh [NEXP * D_OUT * D_IN];        // W in fp16, transposed [e][n][k]

__device__ __forceinline__ uint32_t smem_u32(const void* p) {
    uint32_t a;
    asm("{ .reg .u64 t; cvta.to.shared.u64 t, %1; cvt.u32.u64 %0, t; }" : "=r"(a) : "l"(p));
    return a;
}

// ---------------- kernel 1: W -> fp16 transposed + zero counters ----------------
__global__ void convert_w_kernel(const float* __restrict__ eW) {
    if (blockIdx.x == 0 && blockIdx.y == 0 && blockIdx.z == 0 &&
        threadIdx.y == 0 && threadIdx.x < NEXP) g_cnt[threadIdx.x] = 0;

    __shared__ float t[32][33];
    int e = blockIdx.z, k0 = blockIdx.y * 32, n0 = blockIdx.x * 32;
    const float* W = eW + (size_t)e * D_IN * D_OUT;
    __half* Wh = g_Wh + (size_t)e * D_OUT * D_IN;
#pragma unroll
    for (int j = 0; j < 4; j++)
        t[threadIdx.y + j * 8][threadIdx.x] =
            W[(size_t)(k0 + threadIdx.y + j * 8) * D_OUT + n0 + threadIdx.x];
    __syncthreads();
#pragma unroll
    for (int j = 0; j < 4; j++)
        Wh[(size_t)(n0 + threadIdx.y + j * 8) * D_IN + k0 + threadIdx.x] =
            __float2half_rn(t[threadIdx.x][threadIdx.y + j * 8]);
}

// ---------------- kernel 2: gating + x -> fp16 ----------------
__global__ void gate_kernel(const float* __restrict__ x,
                            const float* __restrict__ gW,
                            const float* __restrict__ gb,
                            int NT) {
    __shared__ float sWt[NEXP * D_IN];
    for (int i = threadIdx.x; i < D_IN * NEXP; i += blockDim.x)
        sWt[(i & 7) * D_IN + (i >> 3)] = gW[i];
    __syncthreads();

    int warp = threadIdx.x >> 5, lane = threadIdx.x & 31;
    int token = blockIdx.x * (blockDim.x >> 5) + warp;
    if (token >= NT) return;

    const float4* xr4 = (const float4*)(x + (size_t)token * D_IN);
    uint2* xo = (uint2*)(g_xh + (size_t)token * D_IN);

    float acc[NEXP];
#pragma unroll
    for (int e = 0; e < NEXP; e++) acc[e] = 0.f;

#pragma unroll
    for (int j = 0; j < D_IN / 128; j++) {
        int idx = lane + j * 32;
        float4 v = xr4[idx];
        int k = idx * 4;
#pragma unroll
        for (int e = 0; e < NEXP; e++) {
            const float* w = &sWt[e * D_IN + k];
            acc[e] = fmaf(v.x, w[0], acc[e]);
            acc[e] = fmaf(v.y, w[1], acc[e]);
            acc[e] = fmaf(v.z, w[2], acc[e]);
            acc[e] = fmaf(v.w, w[3], acc[e]);
        }
        __half2 h0 = __floats2half2_rn(v.x, v.y);
        __half2 h1 = __floats2half2_rn(v.z, v.w);
        uint2 u;
        u.x = *(uint32_t*)&h0;  u.y = *(uint32_t*)&h1;
        xo[idx] = u;
    }
#pragma unroll
    for (int off = 16; off > 0; off >>= 1)
#pragma unroll
        for (int e = 0; e < NEXP; e++)
            acc[e] += __shfl_xor_sync(0xffffffffu, acc[e], off);

    if (lane == 0) {
        float l[NEXP];
#pragma unroll
        for (int e = 0; e < NEXP; e++) l[e] = acc[e] + gb[e];
        float m = l[0];
#pragma unroll
        for (int e = 1; e < NEXP; e++) m = fmaxf(m, l[e]);
        float s = 0.f, w[NEXP];
#pragma unroll
        for (int e = 0; e < NEXP; e++) { w[e] = __expf(l[e] - m); s += w[e]; }
        float inv = 1.f / s;
        int i0 = 0;
#pragma unroll
        for (int e = 1; e < NEXP; e++) if (l[e] > l[i0]) i0 = e;
        int i1 = (i0 == 0) ? 1 : 0;
#pragma unroll
        for (int e = 0; e < NEXP; e++) if (e != i0 && l[e] > l[i1]) i1 = e;

        int p0 = atomicAdd(&g_cnt[i0], 1);
        g_tok[i0 * NT_MAX + p0] = token;  g_wt[i0 * NT_MAX + p0] = w[i0] * inv;
        int p1 = atomicAdd(&g_cnt[i1], 1);
        g_tok[i1 * NT_MAX + p1] = token;  g_wt[i1 * NT_MAX + p1] = w[i1] * inv;
    }
}

// ---------------- kernel 3: FP16 mma.sync + ldmatrix, cp.async pipeline ------
// CTA tile M=128, N=256 (full D_OUT), BK=32 halfs. 8 warps (2m x 4n), warp 64x64.
// A smem [128 rows][40 halfs] pitch 80B; B smem [256 n][40 halfs].
// ldmatrix phases touch all 32 banks (rows r*20 mod 32 distinct).
#define BKS      32
#define NSTAGE   (D_IN / BKS)     // 24
#define PSTAGES  4
#define A_STAGE  10240            // 128 * 80
#define B_STAGE  20480            // 256 * 80
#define SM_B_OFF (PSTAGES * A_STAGE)               // 40960
#define SM_SZ    (SM_B_OFF + PSTAGES * B_STAGE)    // 122880

#define CP_ASYNC_Z(dst, src, sz) \
    asm volatile("cp.async.cg.shared.global [%0], [%1], 16, %2;" \
                 :: "r"(dst), "l"(src), "r"(sz) : "memory")
#define CP_ASYNC16(dst, src) \
    asm volatile("cp.async.cg.shared.global [%0], [%1], 16;" \
                 :: "r"(dst), "l"(src) : "memory")
#define CP_COMMIT()  asm volatile("cp.async.commit_group;" ::: "memory")
#define CP_WAIT(n)   asm volatile("cp.async.wait_group %0;" :: "n"(n) : "memory")

#define LDSM_X4(r0, r1, r2, r3, addr) \
    asm volatile("ldmatrix.sync.aligned.m8n8.x4.shared.b16 {%0,%1,%2,%3}, [%4];" \
                 : "=r"(r0), "=r"(r1), "=r"(r2), "=r"(r3) : "r"(addr))

__global__ __launch_bounds__(256, 1)
void moe_gemm_f16(const float* __restrict__ eb, float* __restrict__ out) {
    const int e = blockIdx.z;
    const int cnt = g_cnt[e];
    const int mbase = blockIdx.y * 128;
    if (mbase >= cnt) return;

    extern __shared__ __align__(1024) char smem[];
    const uint32_t sb = smem_u32(smem);

    const int tid  = threadIdx.x;
    const int wid  = tid >> 5;
    const int lane = tid & 31;
    const int wm = wid >> 2, wn = wid & 3;        // 2m x 4n
    const int grp = lane >> 2, tig = lane & 3;

    // --- A chunks: 512 slots (128 rows x 4 x 8 halfs), 2 per thread ---
    const __half* asrc[2];
    uint32_t adst[2], asz[2];
#pragma unroll
    for (int i = 0; i < 2; i++) {
        int c = tid + i * 256;
        int r = c >> 2, q = c & 3;
        int grow = mbase + r;
        bool v = grow < cnt;
        asrc[i] = g_xh + (v ? (size_t)g_tok[e * NT_MAX + grow] * D_IN : 0) + q * 8;
        adst[i] = sb + (uint32_t)(r * 80 + q * 16);
        asz[i]  = v ? 16u : 0u;
    }
    // --- B chunks: 1024 slots (256 n x 4 x 8 halfs), 4 per thread ---
    const __half* bsrc[4];
    uint32_t bdst[4];
#pragma unroll
    for (int i = 0; i < 4; i++) {
        int c = tid + i * 256;
        int n = c >> 2, q = c & 3;
        bsrc[i] = g_Wh + ((size_t)e * D_OUT + n) * D_IN + q * 8;
        bdst[i] = sb + SM_B_OFF + (uint32_t)(n * 80 + q * 16);
    }

    // ldmatrix per-lane base offsets (in bytes, within a stage)
    // A: row = wm*64 + mi*16 + (lane&15), col = kk + (lane>>4)*8
    const uint32_t aRow = (uint32_t)(wm * 64 + (lane & 15));
    const uint32_t aCol = (uint32_t)((lane >> 4) * 8);
    // B: n = wn*64 + nip*16 + (lane&7) + (lane>>4)*8, col = kk + ((lane>>3)&1)*8
    const uint32_t bRow = (uint32_t)(wn * 64 + (lane & 7) + (lane >> 4) * 8);
    const uint32_t bCol = (uint32_t)(((lane >> 3) & 1) * 8);

    float acc[4][8][4];
#pragma unroll
    for (int mi = 0; mi < 4; mi++)
#pragma unroll
        for (int ni = 0; ni < 8; ni++)
#pragma unroll
            for (int c = 0; c < 4; c++) acc[mi][ni][c] = 0.f;

    auto issue = [&](int s) {
        const uint32_t ao = (uint32_t)((s & (PSTAGES - 1)) * A_STAGE);
        const uint32_t bo = (uint32_t)((s & (PSTAGES - 1)) * B_STAGE);
        const int k0 = s * BKS;
#pragma unroll
        for (int i = 0; i < 2; i++) CP_ASYNC_Z(adst[i] + ao, asrc[i] + k0, asz[i]);
#pragma unroll
        for (int i = 0; i < 4; i++) CP_ASYNC16(bdst[i] + bo, bsrc[i] + k0);
    };

#pragma unroll
    for (int s = 0; s < PSTAGES - 1; s++) { issue(s); CP_COMMIT(); }

    for (int t = 0; t < NSTAGE; t++) {
        CP_WAIT(PSTAGES - 2);
        __syncthreads();

        const uint32_t aBase = sb + (uint32_t)((t & (PSTAGES - 1)) * A_STAGE);
        const uint32_t bBase = sb + SM_B_OFF + (uint32_t)((t & (PSTAGES - 1)) * B_STAGE);

#pragma unroll
        for (int kk = 0; kk < BKS; kk += 16) {
            uint32_t a[4][4];
#pragma unroll
            for (int mi = 0; mi < 4; mi++) {
                uint32_t addr = aBase + (aRow + mi * 16) * 80 + (aCol + kk) * 2;
                LDSM_X4(a[mi][0], a[mi][1], a[mi][2], a[mi][3], addr);
            }
            uint32_t b[8][2];
#pragma unroll
            for (int nip = 0; nip < 4; nip++) {
                uint32_t addr = bBase + (bRow + nip * 16) * 80 + (bCol + kk) * 2;
                LDSM_X4(b[nip*2][0], b[nip*2][1], b[nip*2+1][0], b[nip*2+1][1], addr);
            }
#pragma unroll
            for (int ni = 0; ni < 8; ni++)
#pragma unroll
                for (int mi = 0; mi < 4; mi++) {
                    asm volatile(
                        "mma.sync.aligned.m16n8k16.row.col.f32.f16.f16.f32 "
                        "{%0,%1,%2,%3}, {%4,%5,%6,%7}, {%8,%9}, {%0,%1,%2,%3};"
                        : "+f"(acc[mi][ni][0]), "+f"(acc[mi][ni][1]),
                          "+f"(acc[mi][ni][2]), "+f"(acc[mi][ni][3])
                        : "r"(a[mi][0]), "r"(a[mi][1]), "r"(a[mi][2]), "r"(a[mi][3]),
                          "r"(b[ni][0]), "r"(b[ni][1]));
                }
        }

        if (t + PSTAGES - 1 < NSTAGE) issue(t + PSTAGES - 1);
        CP_COMMIT();
    }

    // --- epilogue: out[token] += w * (acc + bias) ---
    float2 bias[8];
#pragma unroll
    for (int ni = 0; ni < 8; ni++)
        bias[ni] = *(const float2*)(eb + e * D_OUT + wn * 64 + ni * 8 + tig * 2);

#pragma unroll
    for (int mi = 0; mi < 4; mi++) {
        int rbase = wm * 64 + mi * 16 + grp;
#pragma unroll
        for (int h = 0; h < 2; h++) {
            int grow = mbase + rbase + h * 8;
            if (grow < cnt) {
                int   token = g_tok[e * NT_MAX + grow];
                float w     = g_wt [e * NT_MAX + grow];
                float* orow = out + (size_t)token * D_OUT + wn * 64 + tig * 2;
#pragma unroll
                for (int ni = 0; ni < 8; ni++) {
                    float v0 = w * (acc[mi][ni][h * 2]     + bias[ni].x);
                    float v1 = w * (acc[mi][ni][h * 2 + 1] + bias[ni].y);
                    asm volatile("red.global.add.v2.f32 [%0], {%1, %2};"
                                 :: "l"(orow + ni * 8), "f"(v0), "f"(v1) : "memory");
                }
            }
        }
    }
}

// ---------------- launch ----------------
extern "C" void kernel_launch(void* const* d_in, const int* in_sizes, int n_in,
                              void* d_out, int out_size) {
    const float* x  = (const float*)d_in[0];
    const float* gW = (const float*)d_in[1];
    const float* gb = (const float*)d_in[2];
    const float* eW = (const float*)d_in[3];
    const float* eb = (const float*)d_in[4];
    float* out = (float*)d_out;

    const int NT = in_sizes[0] / D_IN;   // 32768

    cudaFuncSetAttribute(moe_gemm_f16, cudaFuncAttributeMaxDynamicSharedMemorySize, SM_SZ);

    cudaMemsetAsync(d_out, 0, (size_t)out_size * sizeof(float), 0);

    dim3 tgrid(D_OUT / 32, D_IN / 32, NEXP);
    convert_w_kernel<<<tgrid, dim3(32, 8)>>>(eW);

    gate_kernel<<<(NT + 7) / 8, 256>>>(x, gW, gb, NT);

    dim3 grid(1, (NT + 127) / 128, NEXP);   // early exit on empty m-tiles
    moe_gemm_f16<<<grid, 256, SM_SZ>>>(eb, out);
}

// round 8
// speedup vs baseline: 1.6981x; 1.1414x over previous
#include <cuda_runtime.h>
#include <cuda_fp16.h>
#include <math.h>
#include <stdint.h>

#define D_IN   768
#define D_OUT  256
#define NEXP   8
#define NT_MAX 32768

// ---------------- device scratch (no allocs allowed) ----------------
__device__ int    g_cnt[NEXP];
__device__ int    g_tok[NEXP * NT_MAX];
__device__ float  g_wt [NEXP * NT_MAX];
__device__ __half g_xh [NT_MAX * D_IN];              // x in fp16 (48 MB)
__device__ __half g_Wh [NEXP * D_OUT * D_IN];        // W in fp16, transposed [e][n][k]

__device__ __forceinline__ uint32_t smem_u32(const void* p) {
    uint32_t a;
    asm("{ .reg .u64 t; cvta.to.shared.u64 t, %1; cvt.u32.u64 %0, t; }" : "=r"(a) : "l"(p));
    return a;
}

// ---------------- kernel 1: W -> fp16 transposed + zero counters ----------------
__global__ void convert_w_kernel(const float* __restrict__ eW) {
    if (blockIdx.x == 0 && blockIdx.y == 0 && blockIdx.z == 0 &&
        threadIdx.y == 0 && threadIdx.x < NEXP) g_cnt[threadIdx.x] = 0;

    __shared__ float t[32][33];
    int e = blockIdx.z, k0 = blockIdx.y * 32, n0 = blockIdx.x * 32;
    const float* W = eW + (size_t)e * D_IN * D_OUT;
    __half* Wh = g_Wh + (size_t)e * D_OUT * D_IN;
#pragma unroll
    for (int j = 0; j < 4; j++)
        t[threadIdx.y + j * 8][threadIdx.x] =
            W[(size_t)(k0 + threadIdx.y + j * 8) * D_OUT + n0 + threadIdx.x];
    __syncthreads();
#pragma unroll
    for (int j = 0; j < 4; j++)
        Wh[(size_t)(n0 + threadIdx.y + j * 8) * D_IN + k0 + threadIdx.x] =
            __float2half_rn(t[threadIdx.x][threadIdx.y + j * 8]);
}

// ---------------- kernel 2: gating + x -> fp16 ----------------
__global__ void gate_kernel(const float* __restrict__ x,
                            const float* __restrict__ gW,
                            const float* __restrict__ gb,
                            int NT) {
    __shared__ float sWt[NEXP * D_IN];
    for (int i = threadIdx.x; i < D_IN * NEXP; i += blockDim.x)
        sWt[(i & 7) * D_IN + (i >> 3)] = gW[i];
    __syncthreads();

    int warp = threadIdx.x >> 5, lane = threadIdx.x & 31;
    int token = blockIdx.x * (blockDim.x >> 5) + warp;
    if (token >= NT) return;

    const float4* xr4 = (const float4*)(x + (size_t)token * D_IN);
    uint2* xo = (uint2*)(g_xh + (size_t)token * D_IN);

    float acc[NEXP];
#pragma unroll
    for (int e = 0; e < NEXP; e++) acc[e] = 0.f;

#pragma unroll
    for (int j = 0; j < D_IN / 128; j++) {
        int idx = lane + j * 32;
        float4 v = xr4[idx];
        int k = idx * 4;
#pragma unroll
        for (int e = 0; e < NEXP; e++) {
            const float* w = &sWt[e * D_IN + k];
            acc[e] = fmaf(v.x, w[0], acc[e]);
            acc[e] = fmaf(v.y, w[1], acc[e]);
            acc[e] = fmaf(v.z, w[2], acc[e]);
            acc[e] = fmaf(v.w, w[3], acc[e]);
        }
        __half2 h0 = __floats2half2_rn(v.x, v.y);
        __half2 h1 = __floats2half2_rn(v.z, v.w);
        uint2 u;
        u.x = *(uint32_t*)&h0;  u.y = *(uint32_t*)&h1;
        xo[idx] = u;
    }
#pragma unroll
    for (int off = 16; off > 0; off >>= 1)
#pragma unroll
        for (int e = 0; e < NEXP; e++)
            acc[e] += __shfl_xor_sync(0xffffffffu, acc[e], off);

    if (lane == 0) {
        float l[NEXP];
#pragma unroll
        for (int e = 0; e < NEXP; e++) l[e] = acc[e] + gb[e];
        float m = l[0];
#pragma unroll
        for (int e = 1; e < NEXP; e++) m = fmaxf(m, l[e]);
        float s = 0.f, w[NEXP];
#pragma unroll
        for (int e = 0; e < NEXP; e++) { w[e] = __expf(l[e] - m); s += w[e]; }
        float inv = 1.f / s;
        int i0 = 0;
#pragma unroll
        for (int e = 1; e < NEXP; e++) if (l[e] > l[i0]) i0 = e;
        int i1 = (i0 == 0) ? 1 : 0;
#pragma unroll
        for (int e = 0; e < NEXP; e++) if (e != i0 && l[e] > l[i1]) i1 = e;

        int p0 = atomicAdd(&g_cnt[i0], 1);
        g_tok[i0 * NT_MAX + p0] = token;  g_wt[i0 * NT_MAX + p0] = w[i0] * inv;
        int p1 = atomicAdd(&g_cnt[i1], 1);
        g_tok[i1 * NT_MAX + p1] = token;  g_wt[i1 * NT_MAX + p1] = w[i1] * inv;
    }
}

// ---------------- kernel 3: FP16 mma.sync + ldmatrix, 2 CTA/SM ---------------
// CTA tile M=128, N=128, BK=64 halfs. 8 warps (4m x 2n), warp tile 32x64.
// A smem [128 rows][72 halfs] pitch 144B; B smem [128 n][72 halfs].
#define BKS      64
#define NSTAGE   (D_IN / BKS)     // 12
#define PSTAGES  3
#define A_STAGE  18432            // 128 * 144
#define B_STAGE  18432
#define STAGE_SZ (A_STAGE + B_STAGE)              // 36864
#define SM_SZ    (PSTAGES * STAGE_SZ)             // 110592

#define CP_ASYNC_Z(dst, src, sz) \
    asm volatile("cp.async.cg.shared.global [%0], [%1], 16, %2;" \
                 :: "r"(dst), "l"(src), "r"(sz) : "memory")
#define CP_ASYNC16(dst, src) \
    asm volatile("cp.async.cg.shared.global [%0], [%1], 16;" \
                 :: "r"(dst), "l"(src) : "memory")
#define CP_COMMIT()  asm volatile("cp.async.commit_group;" ::: "memory")
#define CP_WAIT(n)   asm volatile("cp.async.wait_group %0;" :: "n"(n) : "memory")

#define LDSM_X4(r0, r1, r2, r3, addr) \
    asm volatile("ldmatrix.sync.aligned.m8n8.x4.shared.b16 {%0,%1,%2,%3}, [%4];" \
                 : "=r"(r0), "=r"(r1), "=r"(r2), "=r"(r3) : "r"(addr))

__global__ __launch_bounds__(256, 2)
void moe_gemm_f16(const float* __restrict__ eb, float* __restrict__ out) {
    const int e = blockIdx.z;
    const int cnt = g_cnt[e];
    const int mbase = blockIdx.y * 128;
    if (mbase >= cnt) return;
    const int nbase = blockIdx.x * 128;

    extern __shared__ __align__(1024) char smem[];
    const uint32_t sb = smem_u32(smem);

    const int tid  = threadIdx.x;
    const int wid  = tid >> 5;
    const int lane = tid & 31;
    const int wm = wid >> 1, wn = wid & 1;        // 4m x 2n
    const int grp = lane >> 2, tig = lane & 3;

    // --- A chunks: 1024 slots (128 rows x 8 x 8 halfs), 4 per thread ---
    uint32_t aoff[4];   // byte offsets into g_xh (48MB, fits u32)
    uint32_t adst[4], asz[4];
    const char* xhBase = (const char*)g_xh;
#pragma unroll
    for (int i = 0; i < 4; i++) {
        int c = tid + i * 256;
        int r = c >> 3, q = c & 7;
        int grow = mbase + r;
        bool v = grow < cnt;
        aoff[i] = (uint32_t)((v ? (size_t)g_tok[e * NT_MAX + grow] * D_IN : 0) * 2 + q * 16);
        adst[i] = sb + (uint32_t)(r * 144 + q * 16);
        asz[i]  = v ? 16u : 0u;
    }
    // --- B chunks: 1024 slots (128 n x 8 x 8 halfs), 4 per thread ---
    uint32_t boff[4], bdst[4];
    const char* whBase = (const char*)g_Wh;
#pragma unroll
    for (int i = 0; i < 4; i++) {
        int c = tid + i * 256;
        int n = c >> 3, q = c & 7;
        boff[i] = (uint32_t)((((size_t)e * D_OUT + nbase + n) * D_IN) * 2 + q * 16);
        bdst[i] = sb + (uint32_t)(A_STAGE + n * 144 + q * 16);
    }

    // ldmatrix per-lane bases
    const uint32_t aRow = (uint32_t)(wm * 32 + (lane & 15));
    const uint32_t aCol = (uint32_t)((lane >> 4) * 8);
    const uint32_t bRow = (uint32_t)(wn * 64 + (lane & 7) + (lane >> 4) * 8);
    const uint32_t bCol = (uint32_t)(((lane >> 3) & 1) * 8);

    float acc[2][8][4];
#pragma unroll
    for (int mi = 0; mi < 2; mi++)
#pragma unroll
        for (int ni = 0; ni < 8; ni++)
#pragma unroll
            for (int c = 0; c < 4; c++) acc[mi][ni][c] = 0.f;

    // issue stage s into smem slot sl (caller maintains sl = s mod PSTAGES)
    auto issue = [&](int s, int sl) {
        const uint32_t so = (uint32_t)(sl * STAGE_SZ);
        const uint32_t k0 = (uint32_t)(s * BKS * 2);   // byte offset along k
#pragma unroll
        for (int i = 0; i < 4; i++)
            CP_ASYNC_Z(adst[i] + so, xhBase + aoff[i] + k0, asz[i]);
#pragma unroll
        for (int i = 0; i < 4; i++)
            CP_ASYNC16(bdst[i] + so, whBase + boff[i] + k0);
    };

#pragma unroll
    for (int s = 0; s < PSTAGES - 1; s++) { issue(s, s); CP_COMMIT(); }

    int slot = 0;                       // slot of stage t
    int wslot = PSTAGES - 1;            // slot where stage t+PSTAGES-1 lands
    for (int t = 0; t < NSTAGE; t++) {
        CP_WAIT(PSTAGES - 2);
        __syncthreads();

        const uint32_t aBase = sb + (uint32_t)(slot * STAGE_SZ);
        const uint32_t bBase = aBase + A_STAGE;

#pragma unroll
        for (int kk = 0; kk < BKS; kk += 16) {
            uint32_t a[2][4];
#pragma unroll
            for (int mi = 0; mi < 2; mi++) {
                uint32_t addr = aBase + (aRow + mi * 16) * 144 + (aCol + kk) * 2;
                LDSM_X4(a[mi][0], a[mi][1], a[mi][2], a[mi][3], addr);
            }
            uint32_t b[8][2];
#pragma unroll
            for (int nip = 0; nip < 4; nip++) {
                uint32_t addr = bBase + (bRow + nip * 16) * 144 + (bCol + kk) * 2;
                LDSM_X4(b[nip*2][0], b[nip*2][1], b[nip*2+1][0], b[nip*2+1][1], addr);
            }
#pragma unroll
            for (int ni = 0; ni < 8; ni++)
#pragma unroll
                for (int mi = 0; mi < 2; mi++) {
                    asm volatile(
                        "mma.sync.aligned.m16n8k16.row.col.f32.f16.f16.f32 "
                        "{%0,%1,%2,%3}, {%4,%5,%6,%7}, {%8,%9}, {%0,%1,%2,%3};"
                        : "+f"(acc[mi][ni][0]), "+f"(acc[mi][ni][1]),
                          "+f"(acc[mi][ni][2]), "+f"(acc[mi][ni][3])
                        : "r"(a[mi][0]), "r"(a[mi][1]), "r"(a[mi][2]), "r"(a[mi][3]),
                          "r"(b[ni][0]), "r"(b[ni][1]));
                }
        }

        if (t + PSTAGES - 1 < NSTAGE) issue(t + PSTAGES - 1, wslot);
        CP_COMMIT();
        if (++slot == PSTAGES) slot = 0;
        if (++wslot == PSTAGES) wslot = 0;
    }

    // --- epilogue: shfl-pair into float4, red.global.add.v4 from even-tig ---
    float2 bias[8];
#pragma unroll
    for (int ni = 0; ni < 8; ni++)
        bias[ni] = *(const float2*)(eb + e * D_OUT + nbase + wn * 64 + ni * 8 + tig * 2);

#pragma unroll
    for (int mi = 0; mi < 2; mi++) {
#pragma unroll
        for (int h = 0; h < 2; h++) {
            int grow = mbase + wm * 32 + mi * 16 + grp + h * 8;
            bool valid = grow < cnt;
            int   token = valid ? g_tok[e * NT_MAX + grow] : 0;
            float w     = valid ? g_wt [e * NT_MAX + grow] : 0.f;
            float* orow = out + (size_t)token * D_OUT + nbase + wn * 64;
#pragma unroll
            for (int ni = 0; ni < 8; ni++) {
                float v0 = w * (acc[mi][ni][h * 2]     + bias[ni].x);
                float v1 = w * (acc[mi][ni][h * 2 + 1] + bias[ni].y);
                float p0 = __shfl_xor_sync(0xffffffffu, v0, 1);
                float p1 = __shfl_xor_sync(0xffffffffu, v1, 1);
                if (valid && !(tig & 1)) {
                    // even tig: own cols (tig*2, +1) + partner cols (tig*2+2, +3)
                    asm volatile("red.global.add.v4.f32 [%0], {%1, %2, %3, %4};"
                                 :: "l"(orow + ni * 8 + (tig & 2) * 2),
                                    "f"(v0), "f"(v1), "f"(p0), "f"(p1) : "memory");
                }
            }
        }
    }
}

// ---------------- launch ----------------
extern "C" void kernel_launch(void* const* d_in, const int* in_sizes, int n_in,
                              void* d_out, int out_size) {
    const float* x  = (const float*)d_in[0];
    const float* gW = (const float*)d_in[1];
    const float* gb = (const float*)d_in[2];
    const float* eW = (const float*)d_in[3];
    const float* eb = (const float*)d_in[4];
    float* out = (float*)d_out;

    const int NT = in_sizes[0] / D_IN;   // 32768

    cudaFuncSetAttribute(moe_gemm_f16, cudaFuncAttributeMaxDynamicSharedMemorySize, SM_SZ);

    cudaMemsetAsync(d_out, 0, (size_t)out_size * sizeof(float), 0);

    dim3 tgrid(D_OUT / 32, D_IN / 32, NEXP);
    convert_w_kernel<<<tgrid, dim3(32, 8)>>>(eW);

    gate_kernel<<<(NT + 7) / 8, 256>>>(x, gW, gb, NT);

    dim3 grid(D_OUT / 128, (NT + 127) / 128, NEXP);   // early exit on empty m-tiles
    moe_gemm_f16<<<grid, 256, SM_SZ>>>(eb, out);
}

// round 9
// speedup vs baseline: 1.7256x; 1.0162x over previous
#include <cuda_runtime.h>
#include <cuda_fp16.h>
#include <math.h>
#include <stdint.h>

#define D_IN   768
#define D_OUT  256
#define NEXP   8
#define NT_MAX 32768

// ---------------- device scratch (no allocs allowed) ----------------
__device__ int    g_cnt[NEXP];
__device__ int    g_ticket;
__device__ int    g_tok[NEXP * NT_MAX];
__device__ float  g_wt [NEXP * NT_MAX];
__device__ __half g_xh [NT_MAX * D_IN];              // x in fp16 (48 MB)
__device__ __half g_Wh [NEXP * D_OUT * D_IN];        // W in fp16, transposed [e][n][k]

__device__ __forceinline__ uint32_t smem_u32(const void* p) {
    uint32_t a;
    asm("{ .reg .u64 t; cvta.to.shared.u64 t, %1; cvt.u32.u64 %0, t; }" : "=r"(a) : "l"(p));
    return a;
}

// ---------------- kernel 1: W -> fp16 transposed + zero counters ----------------
__global__ void convert_w_kernel(const float* __restrict__ eW) {
    if (blockIdx.x == 0 && blockIdx.y == 0 && blockIdx.z == 0 && threadIdx.y == 0) {
        if (threadIdx.x < NEXP) g_cnt[threadIdx.x] = 0;
        if (threadIdx.x == NEXP) g_ticket = 0;
    }

    __shared__ float t[32][33];
    int e = blockIdx.z, k0 = blockIdx.y * 32, n0 = blockIdx.x * 32;
    const float* W = eW + (size_t)e * D_IN * D_OUT;
    __half* Wh = g_Wh + (size_t)e * D_OUT * D_IN;
#pragma unroll
    for (int j = 0; j < 4; j++)
        t[threadIdx.y + j * 8][threadIdx.x] =
            W[(size_t)(k0 + threadIdx.y + j * 8) * D_OUT + n0 + threadIdx.x];
    __syncthreads();
#pragma unroll
    for (int j = 0; j < 4; j++)
        Wh[(size_t)(n0 + threadIdx.y + j * 8) * D_IN + k0 + threadIdx.x] =
            __float2half_rn(t[threadIdx.x][threadIdx.y + j * 8]);
}

// ---------------- kernel 2: gating + x -> fp16 ----------------
__global__ void gate_kernel(const float* __restrict__ x,
                            const float* __restrict__ gW,
                            const float* __restrict__ gb,
                            int NT) {
    __shared__ float sWt[NEXP * D_IN];
    for (int i = threadIdx.x; i < D_IN * NEXP; i += blockDim.x)
        sWt[(i & 7) * D_IN + (i >> 3)] = gW[i];
    __syncthreads();

    int warp = threadIdx.x >> 5, lane = threadIdx.x & 31;
    int token = blockIdx.x * (blockDim.x >> 5) + warp;
    if (token >= NT) return;

    const float4* xr4 = (const float4*)(x + (size_t)token * D_IN);
    uint2* xo = (uint2*)(g_xh + (size_t)token * D_IN);

    float acc[NEXP];
#pragma unroll
    for (int e = 0; e < NEXP; e++) acc[e] = 0.f;

#pragma unroll
    for (int j = 0; j < D_IN / 128; j++) {
        int idx = lane + j * 32;
        float4 v = xr4[idx];
        int k = idx * 4;
#pragma unroll
        for (int e = 0; e < NEXP; e++) {
            const float* w = &sWt[e * D_IN + k];
            acc[e] = fmaf(v.x, w[0], acc[e]);
            acc[e] = fmaf(v.y, w[1], acc[e]);
            acc[e] = fmaf(v.z, w[2], acc[e]);
            acc[e] = fmaf(v.w, w[3], acc[e]);
        }
        __half2 h0 = __floats2half2_rn(v.x, v.y);
        __half2 h1 = __floats2half2_rn(v.z, v.w);
        uint2 u;
        u.x = *(uint32_t*)&h0;  u.y = *(uint32_t*)&h1;
        xo[idx] = u;
    }
#pragma unroll
    for (int off = 16; off > 0; off >>= 1)
#pragma unroll
        for (int e = 0; e < NEXP; e++)
            acc[e] += __shfl_xor_sync(0xffffffffu, acc[e], off);

    if (lane == 0) {
        float l[NEXP];
#pragma unroll
        for (int e = 0; e < NEXP; e++) l[e] = acc[e] + gb[e];
        float m = l[0];
#pragma unroll
        for (int e = 1; e < NEXP; e++) m = fmaxf(m, l[e]);
        float s = 0.f, w[NEXP];
#pragma unroll
        for (int e = 0; e < NEXP; e++) { w[e] = __expf(l[e] - m); s += w[e]; }
        float inv = 1.f / s;
        int i0 = 0;
#pragma unroll
        for (int e = 1; e < NEXP; e++) if (l[e] > l[i0]) i0 = e;
        int i1 = (i0 == 0) ? 1 : 0;
#pragma unroll
        for (int e = 0; e < NEXP; e++) if (e != i0 && l[e] > l[i1]) i1 = e;

        int p0 = atomicAdd(&g_cnt[i0], 1);
        g_tok[i0 * NT_MAX + p0] = token;  g_wt[i0 * NT_MAX + p0] = w[i0] * inv;
        int p1 = atomicAdd(&g_cnt[i1], 1);
        g_tok[i1 * NT_MAX + p1] = token;  g_wt[i1 * NT_MAX + p1] = w[i1] * inv;
    }
}

// ---------------- kernel 3: persistent FP16 mma.sync + ldmatrix, 2 CTA/SM ----
// Tile M=128, N=128, BK=64 halfs. 8 warps (4m x 2n), warp tile 32x64.
// A smem [128 rows][72 halfs] pitch 144B; B smem [128 n][72 halfs].
#define BKS      64
#define NSTAGE   (D_IN / BKS)     // 12
#define PSTAGES  3
#define A_STAGE  18432            // 128 * 144
#define B_STAGE  18432
#define STAGE_SZ (A_STAGE + B_STAGE)              // 36864
#define SM_SZ    (PSTAGES * STAGE_SZ)             // 110592
#define NCTAS    296              // 148 SMs x 2

#define CP_ASYNC_Z(dst, src, sz) \
    asm volatile("cp.async.cg.shared.global [%0], [%1], 16, %2;" \
                 :: "r"(dst), "l"(src), "r"(sz) : "memory")
#define CP_ASYNC16(dst, src) \
    asm volatile("cp.async.cg.shared.global [%0], [%1], 16;" \
                 :: "r"(dst), "l"(src) : "memory")
#define CP_COMMIT()  asm volatile("cp.async.commit_group;" ::: "memory")
#define CP_WAIT(n)   asm volatile("cp.async.wait_group %0;" :: "n"(n) : "memory")

#define LDSM_X4(r0, r1, r2, r3, addr) \
    asm volatile("ldmatrix.sync.aligned.m8n8.x4.shared.b16 {%0,%1,%2,%3}, [%4];" \
                 : "=r"(r0), "=r"(r1), "=r"(r2), "=r"(r3) : "r"(addr))

__global__ __launch_bounds__(256, 2)
void moe_gemm_f16(const float* __restrict__ eb, float* __restrict__ out) {
    extern __shared__ __align__(1024) char smem[];
    const uint32_t sb = smem_u32(smem);
    __shared__ int sTicket;

    const int tid  = threadIdx.x;
    const int wid  = tid >> 5;
    const int lane = tid & 31;
    const int wm = wid >> 1, wn = wid & 1;        // 4m x 2n
    const int grp = lane >> 2, tig = lane & 3;

    // Per-expert tile prefix (all threads compute identically).
    int cnts[NEXP], pfx[NEXP + 1];
    pfx[0] = 0;
#pragma unroll
    for (int e = 0; e < NEXP; e++) {
        cnts[e] = g_cnt[e];
        pfx[e + 1] = pfx[e] + 2 * ((cnts[e] + 127) >> 7);   // 2 n-tiles per m-tile
    }
    const int totalTiles = pfx[NEXP];

    // ldmatrix per-lane bases (constant across tiles)
    const uint32_t aRow = (uint32_t)(wm * 32 + (lane & 15));
    const uint32_t aCol = (uint32_t)((lane >> 4) * 8);
    const uint32_t bRow = (uint32_t)(wn * 64 + (lane & 7) + (lane >> 4) * 8);
    const uint32_t bCol = (uint32_t)(((lane >> 3) & 1) * 8);

    const char* xhBase = (const char*)g_xh;
    const char* whBase = (const char*)g_Wh;

    // Per-thread constant parts of staging slots
    const int aR = (tid * 1) >> 3;     // base row pattern per i handled below
    (void)aR;

    while (true) {
        if (tid == 0) sTicket = atomicAdd(&g_ticket, 1);
        __syncthreads();
        const int ticket = sTicket;
        if (ticket >= totalTiles) break;

        // decode ticket -> (e, mtile, ntile)
        int e = 0;
#pragma unroll
        for (int k = 1; k < NEXP; k++) if (ticket >= pfx[k]) e = k;
        const int local  = ticket - pfx[e];
        const int ntile  = local & 1;
        const int mbase  = (local >> 1) * 128;
        const int nbase  = ntile * 128;
        const int cnt    = cnts[e];

        // --- staging descriptors for this tile ---
        uint32_t aoff[4], adst[4], asz[4];
#pragma unroll
        for (int i = 0; i < 4; i++) {
            int c = tid + i * 256;
            int r = c >> 3, q = c & 7;
            int grow = mbase + r;
            bool v = grow < cnt;
            aoff[i] = (uint32_t)((v ? (size_t)g_tok[e * NT_MAX + grow] * D_IN : 0) * 2 + q * 16);
            adst[i] = sb + (uint32_t)(r * 144 + q * 16);
            asz[i]  = v ? 16u : 0u;
        }
        uint32_t boff[4], bdst[4];
#pragma unroll
        for (int i = 0; i < 4; i++) {
            int c = tid + i * 256;
            int n = c >> 3, q = c & 7;
            boff[i] = (uint32_t)((((size_t)e * D_OUT + nbase + n) * D_IN) * 2 + q * 16);
            bdst[i] = sb + (uint32_t)(A_STAGE + n * 144 + q * 16);
        }

        float acc[2][8][4];
#pragma unroll
        for (int mi = 0; mi < 2; mi++)
#pragma unroll
            for (int ni = 0; ni < 8; ni++)
#pragma unroll
                for (int c = 0; c < 4; c++) acc[mi][ni][c] = 0.f;

        auto issue = [&](int s, int sl) {
            const uint32_t so = (uint32_t)(sl * STAGE_SZ);
            const uint32_t k0 = (uint32_t)(s * BKS * 2);
#pragma unroll
            for (int i = 0; i < 4; i++)
                CP_ASYNC_Z(adst[i] + so, xhBase + aoff[i] + k0, asz[i]);
#pragma unroll
            for (int i = 0; i < 4; i++)
                CP_ASYNC16(bdst[i] + so, whBase + boff[i] + k0);
        };

#pragma unroll
        for (int s = 0; s < PSTAGES - 1; s++) { issue(s, s); CP_COMMIT(); }

        int slot = 0, wslot = PSTAGES - 1;
        for (int t = 0; t < NSTAGE; t++) {
            CP_WAIT(PSTAGES - 2);
            __syncthreads();

            const uint32_t aBase = sb + (uint32_t)(slot * STAGE_SZ);
            const uint32_t bBase = aBase + A_STAGE;

#pragma unroll
            for (int kk = 0; kk < BKS; kk += 16) {
                uint32_t a[2][4];
#pragma unroll
                for (int mi = 0; mi < 2; mi++) {
                    uint32_t addr = aBase + (aRow + mi * 16) * 144 + (aCol + kk) * 2;
                    LDSM_X4(a[mi][0], a[mi][1], a[mi][2], a[mi][3], addr);
                }
                uint32_t b[8][2];
#pragma unroll
                for (int nip = 0; nip < 4; nip++) {
                    uint32_t addr = bBase + (bRow + nip * 16) * 144 + (bCol + kk) * 2;
                    LDSM_X4(b[nip*2][0], b[nip*2][1], b[nip*2+1][0], b[nip*2+1][1], addr);
                }
#pragma unroll
                for (int ni = 0; ni < 8; ni++)
#pragma unroll
                    for (int mi = 0; mi < 2; mi++) {
                        asm volatile(
                            "mma.sync.aligned.m16n8k16.row.col.f32.f16.f16.f32 "
                            "{%0,%1,%2,%3}, {%4,%5,%6,%7}, {%8,%9}, {%0,%1,%2,%3};"
                            : "+f"(acc[mi][ni][0]), "+f"(acc[mi][ni][1]),
                              "+f"(acc[mi][ni][2]), "+f"(acc[mi][ni][3])
                            : "r"(a[mi][0]), "r"(a[mi][1]), "r"(a[mi][2]), "r"(a[mi][3]),
                              "r"(b[ni][0]), "r"(b[ni][1]));
                    }
            }

            if (t + PSTAGES - 1 < NSTAGE) issue(t + PSTAGES - 1, wslot);
            CP_COMMIT();
            if (++slot == PSTAGES) slot = 0;
            if (++wslot == PSTAGES) wslot = 0;
        }

        // --- epilogue: shfl-pair, red.global.add.v4 from even-tig ---
        float2 bias[8];
#pragma unroll
        for (int ni = 0; ni < 8; ni++)
            bias[ni] = *(const float2*)(eb + e * D_OUT + nbase + wn * 64 + ni * 8 + tig * 2);

#pragma unroll
        for (int mi = 0; mi < 2; mi++) {
#pragma unroll
            for (int h = 0; h < 2; h++) {
                int grow = mbase + wm * 32 + mi * 16 + grp + h * 8;
                bool valid = grow < cnt;
                int   token = valid ? g_tok[e * NT_MAX + grow] : 0;
                float w     = valid ? g_wt [e * NT_MAX + grow] : 0.f;
                float* orow = out + (size_t)token * D_OUT + nbase + wn * 64;
#pragma unroll
                for (int ni = 0; ni < 8; ni++) {
                    float v0 = w * (acc[mi][ni][h * 2]     + bias[ni].x);
                    float v1 = w * (acc[mi][ni][h * 2 + 1] + bias[ni].y);
                    float p0 = __shfl_xor_sync(0xffffffffu, v0, 1);
                    float p1 = __shfl_xor_sync(0xffffffffu, v1, 1);
                    if (valid && !(tig & 1)) {
                        asm volatile("red.global.add.v4.f32 [%0], {%1, %2, %3, %4};"
                                     :: "l"(orow + ni * 8 + (tig & 2) * 2),
                                        "f"(v0), "f"(v1), "f"(p0), "f"(p1) : "memory");
                    }
                }
            }
        }

        // drain pending cp.async groups before next tile re-stages smem
        CP_WAIT(0);
        __syncthreads();
    }
}

// ---------------- launch ----------------
extern "C" void kernel_launch(void* const* d_in, const int* in_sizes, int n_in,
                              void* d_out, int out_size) {
    const float* x  = (const float*)d_in[0];
    const float* gW = (const float*)d_in[1];
    const float* gb = (const float*)d_in[2];
    const float* eW = (const float*)d_in[3];
    const float* eb = (const float*)d_in[4];
    float* out = (float*)d_out;

    const int NT = in_sizes[0] / D_IN;   // 32768

    cudaFuncSetAttribute(moe_gemm_f16, cudaFuncAttributeMaxDynamicSharedMemorySize, SM_SZ);

    cudaMemsetAsync(d_out, 0, (size_t)out_size * sizeof(float), 0);

    dim3 tgrid(D_OUT / 32, D_IN / 32, NEXP);
    convert_w_kernel<<<tgrid, dim3(32, 8)>>>(eW);

    gate_kernel<<<(NT + 7) / 8, 256>>>(x, gW, gb, NT);

    moe_gemm_f16<<<NCTAS, 256, SM_SZ>>>(eb, out);
}

// round 10
// speedup vs baseline: 1.7636x; 1.0220x over previous
#include <cuda_runtime.h>
#include <cuda_fp16.h>
#include <math.h>
#include <stdint.h>

#define D_IN   768
#define D_OUT  256
#define NEXP   8
#define NT_MAX 32768
#define NCTAS  296                 // 148 SMs x 2

// ---------------- device scratch (no allocs; zero-initialized at load) -------
__device__ int    g_cnt[NEXP];
__device__ int    g_ticket;
__device__ int    g_done;
__device__ int    g_tok[NEXP * NT_MAX];
__device__ float  g_wt [NEXP * NT_MAX];
__device__ __half g_xh [NT_MAX * D_IN];              // x in fp16 (48 MB)
__device__ __half g_Wh [NEXP * D_OUT * D_IN];        // W in fp16, transposed [e][n][k]

__device__ __forceinline__ uint32_t smem_u32(const void* p) {
    uint32_t a;
    asm("{ .reg .u64 t; cvta.to.shared.u64 t, %1; cvt.u32.u64 %0, t; }" : "=r"(a) : "l"(p));
    return a;
}

// ---------------- kernel 1 (merged): convert W  +  gate + zero-out ----------
// blocks [0, 1536): W transpose+fp16.  blocks [1536, 1536+NT/8): gating.
#define CONV_BLOCKS (NEXP * (D_IN / 32) * (D_OUT / 32))   // 1536

__global__ __launch_bounds__(256)
void prep_kernel(const float* __restrict__ x,
                 const float* __restrict__ gW,
                 const float* __restrict__ gb,
                 const float* __restrict__ eW,
                 float* __restrict__ out,
                 int NT) {
    const int tid = threadIdx.x;

    if (blockIdx.x < CONV_BLOCKS) {
        // ---- W convert/transpose ----
        __shared__ float t[32][33];
        int idx = blockIdx.x;
        int e   = idx / 192;
        int rem = idx - e * 192;
        int k0  = (rem >> 3) * 32;          // 24 k-tiles
        int n0  = (rem & 7) * 32;           // 8 n-tiles
        int tx = tid & 31, ty = tid >> 5;   // 32 x 8
        const float* W = eW + (size_t)e * D_IN * D_OUT;
        __half* Wh = g_Wh + (size_t)e * D_OUT * D_IN;
#pragma unroll
        for (int j = 0; j < 4; j++)
            t[ty + j * 8][tx] = W[(size_t)(k0 + ty + j * 8) * D_OUT + n0 + tx];
        __syncthreads();
#pragma unroll
        for (int j = 0; j < 4; j++)
            Wh[(size_t)(n0 + ty + j * 8) * D_IN + k0 + tx] =
                __float2half_rn(t[tx][ty + j * 8]);
        return;
    }

    // ---- gating (one warp per token) + x->fp16 + zero out row ----
    __shared__ float sWt[NEXP * D_IN];
    for (int i = tid; i < D_IN * NEXP; i += blockDim.x)
        sWt[(i & 7) * D_IN + (i >> 3)] = gW[i];
    __syncthreads();

    int warp = tid >> 5, lane = tid & 31;
    int token = (blockIdx.x - CONV_BLOCKS) * 8 + warp;
    if (token >= NT) return;

    // zero this token's output row (256 floats): 2 x float4 per lane
    {
        float4 z = make_float4(0.f, 0.f, 0.f, 0.f);
        float4* orow = (float4*)(out + (size_t)token * D_OUT);
        orow[lane]      = z;
        orow[lane + 32] = z;
    }

    const float4* xr4 = (const float4*)(x + (size_t)token * D_IN);
    uint2* xo = (uint2*)(g_xh + (size_t)token * D_IN);

    float acc[NEXP];
#pragma unroll
    for (int e = 0; e < NEXP; e++) acc[e] = 0.f;

#pragma unroll
    for (int j = 0; j < D_IN / 128; j++) {
        int idx = lane + j * 32;
        float4 v = xr4[idx];
        int k = idx * 4;
#pragma unroll
        for (int e = 0; e < NEXP; e++) {
            const float* w = &sWt[e * D_IN + k];
            acc[e] = fmaf(v.x, w[0], acc[e]);
            acc[e] = fmaf(v.y, w[1], acc[e]);
            acc[e] = fmaf(v.z, w[2], acc[e]);
            acc[e] = fmaf(v.w, w[3], acc[e]);
        }
        __half2 h0 = __floats2half2_rn(v.x, v.y);
        __half2 h1 = __floats2half2_rn(v.z, v.w);
        uint2 u;
        u.x = *(uint32_t*)&h0;  u.y = *(uint32_t*)&h1;
        xo[idx] = u;
    }
#pragma unroll
    for (int off = 16; off > 0; off >>= 1)
#pragma unroll
        for (int e = 0; e < NEXP; e++)
            acc[e] += __shfl_xor_sync(0xffffffffu, acc[e], off);

    if (lane == 0) {
        float l[NEXP];
#pragma unroll
        for (int e = 0; e < NEXP; e++) l[e] = acc[e] + gb[e];
        float m = l[0];
#pragma unroll
        for (int e = 1; e < NEXP; e++) m = fmaxf(m, l[e]);
        float s = 0.f, w[NEXP];
#pragma unroll
        for (int e = 0; e < NEXP; e++) { w[e] = __expf(l[e] - m); s += w[e]; }
        float inv = 1.f / s;
        int i0 = 0;
#pragma unroll
        for (int e = 1; e < NEXP; e++) if (l[e] > l[i0]) i0 = e;
        int i1 = (i0 == 0) ? 1 : 0;
#pragma unroll
        for (int e = 0; e < NEXP; e++) if (e != i0 && l[e] > l[i1]) i1 = e;

        int p0 = atomicAdd(&g_cnt[i0], 1);
        g_tok[i0 * NT_MAX + p0] = token;  g_wt[i0 * NT_MAX + p0] = w[i0] * inv;
        int p1 = atomicAdd(&g_cnt[i1], 1);
        g_tok[i1 * NT_MAX + p1] = token;  g_wt[i1 * NT_MAX + p1] = w[i1] * inv;
    }
}

// ---------------- kernel 2: persistent FP16 GEMM, cross-tile prefetch -------
#define BKS      64
#define NSTAGE   (D_IN / BKS)     // 12
#define PSTAGES  3
#define A_STAGE  18432            // 128 * 144
#define B_STAGE  18432
#define STAGE_SZ (A_STAGE + B_STAGE)
#define SM_SZ    (PSTAGES * STAGE_SZ)             // 110592

#define CP_ASYNC_Z(dst, src, sz) \
    asm volatile("cp.async.cg.shared.global [%0], [%1], 16, %2;" \
                 :: "r"(dst), "l"(src), "r"(sz) : "memory")
#define CP_ASYNC16(dst, src) \
    asm volatile("cp.async.cg.shared.global [%0], [%1], 16;" \
                 :: "r"(dst), "l"(src) : "memory")
#define CP_COMMIT()  asm volatile("cp.async.commit_group;" ::: "memory")
#define CP_WAIT(n)   asm volatile("cp.async.wait_group %0;" :: "n"(n) : "memory")

#define LDSM_X4(r0, r1, r2, r3, addr) \
    asm volatile("ldmatrix.sync.aligned.m8n8.x4.shared.b16 {%0,%1,%2,%3}, [%4];" \
                 : "=r"(r0), "=r"(r1), "=r"(r2), "=r"(r3) : "r"(addr))

__global__ __launch_bounds__(256, 2)
void moe_gemm_f16(const float* __restrict__ eb, float* __restrict__ out) {
    extern __shared__ __align__(1024) char smem[];
    const uint32_t sb = smem_u32(smem);
    __shared__ int sTicket;

    const int tid  = threadIdx.x;
    const int wid  = tid >> 5;
    const int lane = tid & 31;
    const int wm = wid >> 1, wn = wid & 1;        // 4m x 2n
    const int grp = lane >> 2, tig = lane & 3;

    int cnts[NEXP], pfx[NEXP + 1];
    pfx[0] = 0;
#pragma unroll
    for (int e = 0; e < NEXP; e++) {
        cnts[e] = g_cnt[e];
        pfx[e + 1] = pfx[e] + 2 * ((cnts[e] + 127) >> 7);
    }
    const int totalTiles = pfx[NEXP];

    const uint32_t aRow = (uint32_t)(wm * 32 + (lane & 15));
    const uint32_t aCol = (uint32_t)((lane >> 4) * 8);
    const uint32_t bRow = (uint32_t)(wn * 64 + (lane & 7) + (lane >> 4) * 8);
    const uint32_t bCol = (uint32_t)(((lane >> 3) & 1) * 8);

    const char* xhBase = (const char*)g_xh;
    const char* whBase = (const char*)g_Wh;

    uint32_t aoff[4], adst[4], asz[4], boff[4], bdst[4];

    // decode ticket -> scalars; build staging descriptors; issue stages 0,1
    auto setupTile = [&](int ticket, int& e, int& mbase, int& nbase, int& cnt) {
        e = 0;
#pragma unroll
        for (int k = 1; k < NEXP; k++) if (ticket >= pfx[k]) e = k;
        const int local = ticket - pfx[e];
        nbase = (local & 1) * 128;
        mbase = (local >> 1) * 128;
        cnt   = cnts[e];
#pragma unroll
        for (int i = 0; i < 4; i++) {
            int c = tid + i * 256;
            int r = c >> 3, q = c & 7;
            int grow = mbase + r;
            bool v = grow < cnt;
            aoff[i] = (uint32_t)((v ? (size_t)g_tok[e * NT_MAX + grow] * D_IN : 0) * 2 + q * 16);
            adst[i] = sb + (uint32_t)(r * 144 + q * 16);
            asz[i]  = v ? 16u : 0u;
        }
#pragma unroll
        for (int i = 0; i < 4; i++) {
            int c = tid + i * 256;
            int n = c >> 3, q = c & 7;
            boff[i] = (uint32_t)((((size_t)e * D_OUT + nbase + n) * D_IN) * 2 + q * 16);
            bdst[i] = sb + (uint32_t)(A_STAGE + n * 144 + q * 16);
        }
    };
    auto issue = [&](int s, int sl) {
        const uint32_t so = (uint32_t)(sl * STAGE_SZ);
        const uint32_t k0 = (uint32_t)(s * BKS * 2);
#pragma unroll
        for (int i = 0; i < 4; i++)
            CP_ASYNC_Z(adst[i] + so, xhBase + aoff[i] + k0, asz[i]);
#pragma unroll
        for (int i = 0; i < 4; i++)
            CP_ASYNC16(bdst[i] + so, whBase + boff[i] + k0);
    };

    if (tid == 0) sTicket = atomicAdd(&g_ticket, 1);
    __syncthreads();
    int ticket = sTicket;
    int curE = 0, curM = 0, curN = 0, curCnt = 0;
    bool have = ticket < totalTiles;
    if (have) {
        setupTile(ticket, curE, curM, curN, curCnt);
        issue(0, 0); CP_COMMIT();
        issue(1, 1); CP_COMMIT();
    }

    while (have) {
        float acc[2][8][4];
#pragma unroll
        for (int mi = 0; mi < 2; mi++)
#pragma unroll
            for (int ni = 0; ni < 8; ni++)
#pragma unroll
                for (int c = 0; c < 4; c++) acc[mi][ni][c] = 0.f;

        int slot = 0, wslot = PSTAGES - 1;
        for (int t = 0; t < NSTAGE; t++) {
            CP_WAIT(PSTAGES - 2);
            __syncthreads();

            const uint32_t aBase = sb + (uint32_t)(slot * STAGE_SZ);
            const uint32_t bBase = aBase + A_STAGE;

#pragma unroll
            for (int kk = 0; kk < BKS; kk += 16) {
                uint32_t a[2][4];
#pragma unroll
                for (int mi = 0; mi < 2; mi++) {
                    uint32_t addr = aBase + (aRow + mi * 16) * 144 + (aCol + kk) * 2;
                    LDSM_X4(a[mi][0], a[mi][1], a[mi][2], a[mi][3], addr);
                }
                uint32_t b[8][2];
#pragma unroll
                for (int nip = 0; nip < 4; nip++) {
                    uint32_t addr = bBase + (bRow + nip * 16) * 144 + (bCol + kk) * 2;
                    LDSM_X4(b[nip*2][0], b[nip*2][1], b[nip*2+1][0], b[nip*2+1][1], addr);
                }
#pragma unroll
                for (int ni = 0; ni < 8; ni++)
#pragma unroll
                    for (int mi = 0; mi < 2; mi++) {
                        asm volatile(
                            "mma.sync.aligned.m16n8k16.row.col.f32.f16.f16.f32 "
                            "{%0,%1,%2,%3}, {%4,%5,%6,%7}, {%8,%9}, {%0,%1,%2,%3};"
                            : "+f"(acc[mi][ni][0]), "+f"(acc[mi][ni][1]),
                              "+f"(acc[mi][ni][2]), "+f"(acc[mi][ni][3])
                            : "r"(a[mi][0]), "r"(a[mi][1]), "r"(a[mi][2]), "r"(a[mi][3]),
                              "r"(b[ni][0]), "r"(b[ni][1]));
                    }
            }

            if (t + PSTAGES - 1 < NSTAGE) issue(t + PSTAGES - 1, wslot);
            CP_COMMIT();
            if (++slot == PSTAGES) slot = 0;
            if (++wslot == PSTAGES) wslot = 0;
        }

        // claim next tile; prefetch its prologue BEFORE the epilogue.
        __syncthreads();                       // all warps past stage-11 reads
        if (tid == 0) sTicket = atomicAdd(&g_ticket, 1);
        __syncthreads();
        int nextTicket = sTicket;
        bool haveNext = nextTicket < totalTiles;
        int nE = 0, nM = 0, nN = 0, nCnt = 0;
        if (haveNext) {
            setupTile(nextTicket, nE, nM, nN, nCnt);   // overwrites desc arrays
            issue(0, 0); CP_COMMIT();                  // slots 0,1 dead (last read st. 9,10)
            issue(1, 1); CP_COMMIT();
        }

        // epilogue for current tile (overlaps next-tile DRAM latency)
        {
            float2 bias[8];
#pragma unroll
            for (int ni = 0; ni < 8; ni++)
                bias[ni] = *(const float2*)(eb + curE * D_OUT + curN + wn * 64 + ni * 8 + tig * 2);

#pragma unroll
            for (int mi = 0; mi < 2; mi++) {
#pragma unroll
                for (int h = 0; h < 2; h++) {
                    int grow = curM + wm * 32 + mi * 16 + grp + h * 8;
                    bool valid = grow < curCnt;
                    int   token = valid ? g_tok[curE * NT_MAX + grow] : 0;
                    float w     = valid ? g_wt [curE * NT_MAX + grow] : 0.f;
                    float* orow = out + (size_t)token * D_OUT + curN + wn * 64;
#pragma unroll
                    for (int ni = 0; ni < 8; ni++) {
                        float v0 = w * (acc[mi][ni][h * 2]     + bias[ni].x);
                        float v1 = w * (acc[mi][ni][h * 2 + 1] + bias[ni].y);
                        float p0 = __shfl_xor_sync(0xffffffffu, v0, 1);
                        float p1 = __shfl_xor_sync(0xffffffffu, v1, 1);
                        if (valid && !(tig & 1)) {
                            asm volatile("red.global.add.v4.f32 [%0], {%1, %2, %3, %4};"
                                         :: "l"(orow + ni * 8 + (tig & 2) * 2),
                                            "f"(v0), "f"(v1), "f"(p0), "f"(p1) : "memory");
                        }
                    }
                }
            }
        }

        curE = nE; curM = nM; curN = nN; curCnt = nCnt;
        have = haveNext;
    }

    // self-reset for next graph replay: last CTA to finish clears state.
    __syncthreads();
    if (tid == 0) {
        int d = atomicAdd(&g_done, 1);
        if (d == NCTAS - 1) {
#pragma unroll
            for (int e = 0; e < NEXP; e++) g_cnt[e] = 0;
            g_ticket = 0;
            g_done = 0;
        }
    }
}

// ---------------- launch ----------------
extern "C" void kernel_launch(void* const* d_in, const int* in_sizes, int n_in,
                              void* d_out, int out_size) {
    const float* x  = (const float*)d_in[0];
    const float* gW = (const float*)d_in[1];
    const float* gb = (const float*)d_in[2];
    const float* eW = (const float*)d_in[3];
    const float* eb = (const float*)d_in[4];
    float* out = (float*)d_out;

    const int NT = in_sizes[0] / D_IN;   // 32768

    cudaFuncSetAttribute(moe_gemm_f16, cudaFuncAttributeMaxDynamicSharedMemorySize, SM_SZ);

    prep_kernel<<<CONV_BLOCKS + (NT + 7) / 8, 256>>>(x, gW, gb, eW, out, NT);
    moe_gemm_f16<<<NCTAS, 256, SM_SZ>>>(eb, out);
}